// round 9
// baseline (speedup 1.0000x reference)
#include <cuda_runtime.h>
#include <cuda_bf16.h>
#include <math.h>
#include <stdint.h>

#define T_TOK 2048
#define H_DIM 2048
#define I_DIM 768
#define E_NUM 32
#define K_TOP 8
#define CAP   1024
#define A_TOTAL (T_TOK * K_TOP)
#define N1 (2 * I_DIM)          // 1536

#define TPE1 12                 // gemm1 tiles/expert: 4 mpair x 3 nblk
#define TPE2 16                 // gemm2: 4 mpair x 4 nblk
#define NTIL1 (E_NUM * TPE1)    // 384
#define NTIL2 (E_NUM * TPE2)    // 512
#define NCLUS 74

#if defined(__CUDA_ARCH__)
#  if defined(__CUDA_ARCH_FEAT_SM103_ALL) || defined(__CUDA_ARCH_FEAT_SM100_ALL) || \
      (defined(__CUDA_ARCH_SPECIFIC__) && (__CUDA_ARCH_SPECIFIC__ == 1030 || __CUDA_ARCH_SPECIFIC__ == 1000))
#    define HAS_TCGEN05 1
#  else
#    define HAS_TCGEN05 0
#  endif
#else
#  define HAS_TCGEN05 0
#endif

// ---------------- device scratch ----------------
__device__ float g_gate_wT[E_NUM * H_DIM];
__device__ int   g_cnt[E_NUM];
__device__ int   g_tok[E_NUM * CAP];
__device__ int   g_aid[E_NUM * CAP];
__device__ float g_wgt[E_NUM * CAP];
__device__ int   g_pl1[NTIL1], g_pl2[NTIL2];
__device__ int   g_npl1, g_npl2;
__device__ unsigned short g_hh[(size_t)E_NUM * CAP * I_DIM];
__device__ unsigned short g_hl[(size_t)E_NUM * CAP * I_DIM];
__device__ float g_y[(size_t)A_TOTAL * H_DIM];
__device__ unsigned short g_w1h[(size_t)E_NUM * N1 * H_DIM];
__device__ unsigned short g_w1l[(size_t)E_NUM * N1 * H_DIM];
__device__ unsigned short g_w2h[(size_t)E_NUM * H_DIM * I_DIM];
__device__ unsigned short g_w2l[(size_t)E_NUM * H_DIM * I_DIM];

// ---------------- helpers ----------------
__device__ __forceinline__ void split_bf16(float x, unsigned short& h, unsigned short& l) {
    __nv_bfloat16 bh = __float2bfloat16_rn(x);
    h = *reinterpret_cast<unsigned short*>(&bh);
    float r = x - __bfloat162float(bh);
    __nv_bfloat16 bl = __float2bfloat16_rn(r);
    l = *reinterpret_cast<unsigned short*>(&bl);
}
__device__ __forceinline__ uint32_t smem_u32(const void* p) {
    return (uint32_t)__cvta_generic_to_shared(p);
}
__device__ __forceinline__ uint32_t swz128(uint32_t o) { return o ^ ((o >> 3) & 0x70); }

// ---------------- weight conversion: [E][k][n] fp32 -> [E][n][k] bf16 hi/lo ----------------
template<int KD, int ND>
__global__ __launch_bounds__(256) void conv_kernel(const float* __restrict__ W,
                                                   unsigned short* __restrict__ Wh,
                                                   unsigned short* __restrict__ Wl) {
    const int e = blockIdx.z;
    const int k0 = blockIdx.x * 128;
    const int n0 = blockIdx.y * 64;
    __shared__ float ts[128][65];
    const int tid = threadIdx.x;

    const int lr = tid >> 4, lc = (tid & 15) * 4;
    const float* src = W + (size_t)e * KD * ND + (size_t)k0 * ND + n0;
#pragma unroll
    for (int it = 0; it < 8; it++) {
        const int row = lr + it * 16;
        float4 v = *(const float4*)(src + (size_t)row * ND + lc);
        ts[row][lc + 0] = v.x; ts[row][lc + 1] = v.y;
        ts[row][lc + 2] = v.z; ts[row][lc + 3] = v.w;
    }
    __syncthreads();

    const int n = tid >> 2, ks = (tid & 3) * 32;
    const size_t doff = ((size_t)e * ND + n0 + n) * KD + k0 + ks;
#pragma unroll
    for (int part = 0; part < 2; part++) {
        uint32_t hh[8], ll[8];
#pragma unroll
        for (int q = 0; q < 8; q++) {
            unsigned short h0, h1, l0, l1;
            split_bf16(ts[ks + part * 16 + 2 * q][n],     h0, l0);
            split_bf16(ts[ks + part * 16 + 2 * q + 1][n], h1, l1);
            hh[q] = (uint32_t)h0 | ((uint32_t)h1 << 16);
            ll[q] = (uint32_t)l0 | ((uint32_t)l1 << 16);
        }
        *(uint4*)(Wh + doff + part * 16)     = make_uint4(hh[0], hh[1], hh[2], hh[3]);
        *(uint4*)(Wh + doff + part * 16 + 8) = make_uint4(hh[4], hh[5], hh[6], hh[7]);
        *(uint4*)(Wl + doff + part * 16)     = make_uint4(ll[0], ll[1], ll[2], ll[3]);
        *(uint4*)(Wl + doff + part * 16 + 8) = make_uint4(ll[4], ll[5], ll[6], ll[7]);
    }
}

// ---------------- prep ----------------
__global__ void prep_kernel(const float* __restrict__ gate_w) {
    int i = blockIdx.x * 256 + threadIdx.x;
    if (i < E_NUM * H_DIM) {
        int e = i >> 11;
        int h = i & (H_DIM - 1);
        g_gate_wT[i] = gate_w[h * E_NUM + e];
    }
    if (i < E_NUM) g_cnt[i] = 0;
}

// ---------------- router ----------------
__global__ __launch_bounds__(256) void router_kernel(const float* __restrict__ x,
                                                     const float* __restrict__ gate_b) {
    __shared__ float xs[H_DIM];
    __shared__ float lg[E_NUM];
    const int t = blockIdx.x;
    const int tid = threadIdx.x;

    const float4* xr = (const float4*)(x + (size_t)t * H_DIM);
    for (int i = tid; i < H_DIM / 4; i += 256) ((float4*)xs)[i] = xr[i];
    __syncthreads();

    const int w = tid >> 5, lane = tid & 31;
#pragma unroll
    for (int ee = 0; ee < 4; ee++) {
        const int e = (w << 2) + ee;
        const float* gw = g_gate_wT + (size_t)e * H_DIM;
        float s = 0.f;
        for (int h = lane; h < H_DIM; h += 32) s += xs[h] * gw[h];
#pragma unroll
        for (int off = 16; off; off >>= 1) s += __shfl_xor_sync(0xffffffffu, s, off);
        if (lane == 0) lg[e] = s + gate_b[e];
    }
    __syncthreads();

    if (tid == 0) {
        float mx = lg[0];
#pragma unroll
        for (int e = 1; e < E_NUM; e++) mx = fmaxf(mx, lg[e]);
        float p[E_NUM];
#pragma unroll
        for (int e = 0; e < E_NUM; e++) p[e] = __expf(lg[e] - mx);
        float vals[K_TOP]; int sel[K_TOP]; float vsum = 0.f;
#pragma unroll
        for (int k = 0; k < K_TOP; k++) {
            int bj = 0; float bv = p[0];
            for (int e = 1; e < E_NUM; e++) if (p[e] > bv) { bv = p[e]; bj = e; }
            sel[k] = bj; vals[k] = bv; vsum += bv; p[bj] = -1.f;
        }
        const float inv = 1.f / vsum;
#pragma unroll
        for (int k = 0; k < K_TOP; k++) {
            const int e = sel[k];
            int slot = atomicAdd(&g_cnt[e], 1);
            if (slot < CAP) {
                g_tok[e * CAP + slot] = t;
                g_aid[e * CAP + slot] = (t << 3) + k;
                g_wgt[e * CAP + slot] = vals[k] * inv;
            }
        }
    }
}

// ---------------- plan: compact real tiles ----------------
__global__ void plan_kernel() {
    if (threadIdx.x == 0) {
        int n = 0;
        for (int tl = 0; tl < NTIL1; tl++) {
            int e = tl / TPE1, mpair = (tl % TPE1) & 3;
            if (mpair * 256 < g_cnt[e]) g_pl1[n++] = tl;
        }
        g_npl1 = n;
    } else if (threadIdx.x == 32) {
        int n = 0;
        for (int tl = 0; tl < NTIL2; tl++) {
            int e = tl / TPE2, mpair = (tl % TPE2) & 3;
            if (mpair * 256 < g_cnt[e]) g_pl2[n++] = tl;
        }
        g_npl2 = n;
    }
}

// ---------------- smem arena ----------------
#define SM_TMEMPTR 0
#define SM_RDY     16
#define SM_DONE    32
#define SM_TDONE   48
#define SM_TOKS    64
#define SM_BUF     1024
#define OFF_AH     0
#define OFF_AL     16384
#define OFF_BH     32768       // 4 nb blocks x (64 rows x 128B = 8KB)
#define OFF_BL     65536
#define BUF_SZ     98304
#define SMEM_TC    (SM_BUF + 2 * BUF_SZ)   // 197632

#if HAS_TCGEN05
__device__ __forceinline__ uint32_t elect_one() {
    uint32_t pred;
    asm volatile("{\n\t.reg .pred p;\n\telect.sync _|p, 0xFFFFFFFF;\n\tselp.b32 %0, 1, 0, p;\n\t}"
                 : "=r"(pred));
    return pred;
}
__device__ __forceinline__ uint32_t ctarank() {
    uint32_t r;
    asm("mov.u32 %0, %%cluster_ctarank;" : "=r"(r));
    return r;
}
__device__ __forceinline__ uint64_t desc_k_sw128(uint32_t addr) {
    return ((uint64_t)(addr >> 4) & 0x3FFF) | (1ull << 16) | (64ull << 32)
         | (1ull << 46) | (2ull << 61);
}
// idesc kind::f16 cg2: dtype=F32, atype=BF16, btype=BF16, N=128, M=256
#define MMA_IDESC2 ((1u << 4) | (1u << 7) | (1u << 10) | ((128u / 8) << 17) | ((256u / 16) << 24))

__device__ __forceinline__ void tcg_mma2(uint32_t d, uint64_t a, uint64_t b, uint32_t en) {
    asm volatile(
        "{\n\t.reg .pred p;\n\tsetp.ne.u32 p, %4, 0;\n\t"
        "tcgen05.mma.cta_group::2.kind::f16 [%0], %1, %2, %3, "
        "{%5, %5, %5, %5, %5, %5, %5, %5}, p;\n\t}"
        :: "r"(d), "l"(a), "l"(b), "r"(MMA_IDESC2), "r"(en), "r"(0u) : "memory");
}
__device__ __forceinline__ void tcg_commit_mc2(uint32_t mbar, uint16_t mask) {
    asm volatile(
        "tcgen05.commit.cta_group::2.mbarrier::arrive::one.shared::cluster.multicast::cluster.b64 [%0], %1;"
        :: "r"(mbar), "h"(mask) : "memory");
}
__device__ __forceinline__ void tcg_alloc2(uint32_t smem_res, uint32_t ncols) {
    asm volatile("tcgen05.alloc.cta_group::2.sync.aligned.shared::cta.b32 [%0], %1;"
                 :: "r"(smem_res), "r"(ncols) : "memory");
}
__device__ __forceinline__ void tcg_dealloc2(uint32_t tmem, uint32_t ncols) {
    asm volatile("tcgen05.dealloc.cta_group::2.sync.aligned.b32 %0, %1;" :: "r"(tmem), "r"(ncols));
}
__device__ __forceinline__ void tcg_relinq2() {
    asm volatile("tcgen05.relinquish_alloc_permit.cta_group::2.sync.aligned;");
}
__device__ __forceinline__ void mbar_init(uint32_t mbar, uint32_t cnt) {
    asm volatile("mbarrier.init.shared.b64 [%0], %1;" :: "r"(mbar), "r"(cnt) : "memory");
}
__device__ __forceinline__ void mbar_arrive_rank0(uint32_t addr) {
    asm volatile(
        "{\n\t.reg .b32 r;\n\t"
        "mapa.shared::cluster.u32 r, %0, 0;\n\t"
        "mbarrier.arrive.shared::cluster.b64 _, [r];\n\t}"
        :: "r"(addr) : "memory");
}
__device__ __forceinline__ void mbar_wait(uint32_t mbar, uint32_t parity) {
    uint32_t done;
    asm volatile(
        "{\n\t.reg .pred p;\n\t"
        "mbarrier.try_wait.parity.acquire.cta.shared::cta.b64 p, [%1], %2;\n\t"
        "selp.b32 %0, 1, 0, p;\n\t}"
        : "=r"(done) : "r"(mbar), "r"(parity) : "memory");
    if (!done) {
        asm volatile(
            "{\n\t.reg .pred P1;\n\t"
            "WAIT_LOOP_%=:\n\t"
            "mbarrier.try_wait.parity.acquire.cta.shared::cta.b64 P1, [%0], %1, 0x989680;\n\t"
            "@P1 bra.uni WAIT_DONE_%=;\n\t"
            "bra.uni WAIT_LOOP_%=;\n\t"
            "WAIT_DONE_%=:\n\t}"
            :: "r"(mbar), "r"(parity) : "memory");
    }
}
__device__ __forceinline__ void fence_async_smem() {
    asm volatile("fence.proxy.async.shared::cta;" ::: "memory");
}
__device__ __forceinline__ void tcg_fence_after() {
    asm volatile("tcgen05.fence::after_thread_sync;" ::: "memory");
}
__device__ __forceinline__ void tcg_fence_before() {
    asm volatile("tcgen05.fence::before_thread_sync;" ::: "memory");
}
__device__ __forceinline__ void tcg_wait_ld() {
    asm volatile("tcgen05.wait::ld.sync.aligned;" ::: "memory");
}
__device__ __forceinline__ void cluster_sync_() {
    asm volatile("barrier.cluster.arrive.aligned;" ::: "memory");
    asm volatile("barrier.cluster.wait.aligned;" ::: "memory");
}
__device__ __forceinline__ void ldtm32(uint32_t* r, uint32_t addr) {
    asm volatile(
        "tcgen05.ld.sync.aligned.32x32b.x32.b32 "
        "{%0, %1, %2, %3, %4, %5, %6, %7, "
        " %8, %9, %10, %11, %12, %13, %14, %15, "
        " %16, %17, %18, %19, %20, %21, %22, %23, "
        " %24, %25, %26, %27, %28, %29, %30, %31}, [%32];"
        : "=r"(r[0]),  "=r"(r[1]),  "=r"(r[2]),  "=r"(r[3]),
          "=r"(r[4]),  "=r"(r[5]),  "=r"(r[6]),  "=r"(r[7]),
          "=r"(r[8]),  "=r"(r[9]),  "=r"(r[10]), "=r"(r[11]),
          "=r"(r[12]), "=r"(r[13]), "=r"(r[14]), "=r"(r[15]),
          "=r"(r[16]), "=r"(r[17]), "=r"(r[18]), "=r"(r[19]),
          "=r"(r[20]), "=r"(r[21]), "=r"(r[22]), "=r"(r[23]),
          "=r"(r[24]), "=r"(r[25]), "=r"(r[26]), "=r"(r[27]),
          "=r"(r[28]), "=r"(r[29]), "=r"(r[30]), "=r"(r[31])
        : "r"(addr));
}
#endif  // HAS_TCGEN05

// Persistent 2-CTA tcgen05 grouped GEMM, bf16x3, BM=256/BN=512/Kc=64, N=128/dispatch.
// grid (2, 74, 1), cluster (2,1,1). Tiles from compacted plan.
template<int MODE>
__global__ __launch_bounds__(512) __cluster_dims__(2, 1, 1)
void gemm_tc2(const float* __restrict__ X) {
#if HAS_TCGEN05
    constexpr int KDIM = MODE ? I_DIM : H_DIM;
    constexpr int NC   = KDIM / 64;
    constexpr int TPE  = MODE ? TPE2 : TPE1;

    const uint32_t rank = ctarank();
    const int tid = threadIdx.x;
    const int wid = tid >> 5, lane = tid & 31;

    extern __shared__ __align__(1024) char smem[];
    const uint32_t sb = smem_u32(smem);

    if (wid == 0) tcg_alloc2(sb + SM_TMEMPTR, 512);
    if (tid == 0) {
        mbar_init(sb + SM_RDY, 2);      mbar_init(sb + SM_RDY + 8, 2);
        mbar_init(sb + SM_DONE, 1);     mbar_init(sb + SM_DONE + 8, 1);
        mbar_init(sb + SM_TDONE, 1);
    }
    __syncthreads();
    uint32_t tm;
    asm volatile("ld.shared.b32 %0, [%1];" : "=r"(tm) : "r"(sb + SM_TMEMPTR));
    cluster_sync_();

    uint32_t leader = 0;
    if (rank == 0 && wid == 0) leader = elect_one();

    const int ntiles = MODE ? g_npl2 : g_npl1;
    const int* plan  = MODE ? g_pl2 : g_pl1;

    const int arow = tid >> 2, akq = (tid & 3) * 16;
    const uint32_t a_base = (uint32_t)arow * 128 + (uint32_t)akq * 2;
    const int bl = tid >> 1, bkh = (tid & 1) * 32;
    const int nb_blk = bl >> 6, lr = bl & 63;
    const uint32_t b_base = (uint32_t)bl * 128 + (uint32_t)bkh * 2;

    int cc = 0, dp[2] = {0, 0}, rp[2] = {0, 0}, tp = 0;

    for (int ti = blockIdx.y; ti < ntiles; ti += NCLUS) {
        const int tl = plan[ti];
        const int e = tl / TPE, rr = tl % TPE;
        const int mpair = rr & 3, nblk = rr >> 2;
        const int count = g_cnt[e];
        const int pm0 = mpair * 256;

        // ---- per-tile pointers ----
        const float* arow_f = nullptr;
        const unsigned short *arow_h = nullptr, *arow_l = nullptr;
        if (MODE == 0) {
            if (tid < 128) {
                int s = pm0 + (int)rank * 128 + tid; if (s >= count) s = count - 1;
                ((int*)(smem + SM_TOKS))[tid] = g_tok[e * CAP + s];
            }
            __syncthreads();
            arow_f = X + (size_t)((int*)(smem + SM_TOKS))[arow] * H_DIM + akq;
        } else {
            int s = pm0 + (int)rank * 128 + arow; if (s >= count) s = count - 1;
            size_t off = ((size_t)e * CAP + s) * I_DIM + akq;
            arow_h = g_hh + off; arow_l = g_hl + off;
        }
        int gcol;
        if (MODE == 0) {
            const int is_up = nb_blk & 1, base = (nb_blk >> 1) * 128;
            gcol = (is_up ? I_DIM : 0) + nblk * 256 + base + (int)rank * 64 + lr;
        } else {
            gcol = nblk * 512 + nb_blk * 128 + (int)rank * 64 + lr;
        }
        const unsigned short *bcol_h, *bcol_l;
        if (MODE == 0) {
            size_t off = ((size_t)e * N1 + gcol) * H_DIM + bkh;
            bcol_h = g_w1h + off; bcol_l = g_w1l + off;
        } else {
            size_t off = ((size_t)e * H_DIM + gcol) * I_DIM + bkh;
            bcol_h = g_w2h + off; bcol_l = g_w2l + off;
        }

        // ---- chunk pipeline ----
        for (int c = 0; c < NC; c++, cc++) {
            const int b = cc & 1;
            if (cc >= 2) { mbar_wait(sb + SM_DONE + 8 * b, dp[b]); dp[b] ^= 1; }
            const uint32_t bufb = sb + SM_BUF + b * BUF_SZ;
            const int k0 = c * 64;

            if (MODE == 0) {
                float4 v0 = *(const float4*)(arow_f + k0);
                float4 v1 = *(const float4*)(arow_f + k0 + 4);
                float4 v2 = *(const float4*)(arow_f + k0 + 8);
                float4 v3 = *(const float4*)(arow_f + k0 + 12);
                float vv[16] = {v0.x,v0.y,v0.z,v0.w, v1.x,v1.y,v1.z,v1.w,
                                v2.x,v2.y,v2.z,v2.w, v3.x,v3.y,v3.z,v3.w};
                uint32_t hh[8], ll[8];
#pragma unroll
                for (int q = 0; q < 8; q++) {
                    unsigned short h0, h1, l0, l1;
                    split_bf16(vv[2*q],   h0, l0);
                    split_bf16(vv[2*q+1], h1, l1);
                    hh[q] = (uint32_t)h0 | ((uint32_t)h1 << 16);
                    ll[q] = (uint32_t)l0 | ((uint32_t)l1 << 16);
                }
                const uint32_t s0 = swz128(a_base), s1 = swz128(a_base + 16);
                asm volatile("st.shared.v4.b32 [%0], {%1,%2,%3,%4};"
                             :: "r"(bufb + OFF_AH + s0), "r"(hh[0]), "r"(hh[1]), "r"(hh[2]), "r"(hh[3]));
                asm volatile("st.shared.v4.b32 [%0], {%1,%2,%3,%4};"
                             :: "r"(bufb + OFF_AH + s1), "r"(hh[4]), "r"(hh[5]), "r"(hh[6]), "r"(hh[7]));
                asm volatile("st.shared.v4.b32 [%0], {%1,%2,%3,%4};"
                             :: "r"(bufb + OFF_AL + s0), "r"(ll[0]), "r"(ll[1]), "r"(ll[2]), "r"(ll[3]));
                asm volatile("st.shared.v4.b32 [%0], {%1,%2,%3,%4};"
                             :: "r"(bufb + OFF_AL + s1), "r"(ll[4]), "r"(ll[5]), "r"(ll[6]), "r"(ll[7]));
            } else {
                uint4 vh0 = *(const uint4*)(arow_h + k0);
                uint4 vh1 = *(const uint4*)(arow_h + k0 + 8);
                uint4 vl0 = *(const uint4*)(arow_l + k0);
                uint4 vl1 = *(const uint4*)(arow_l + k0 + 8);
                const uint32_t s0 = swz128(a_base), s1 = swz128(a_base + 16);
                asm volatile("st.shared.v4.b32 [%0], {%1,%2,%3,%4};"
                             :: "r"(bufb + OFF_AH + s0), "r"(vh0.x), "r"(vh0.y), "r"(vh0.z), "r"(vh0.w));
                asm volatile("st.shared.v4.b32 [%0], {%1,%2,%3,%4};"
                             :: "r"(bufb + OFF_AH + s1), "r"(vh1.x), "r"(vh1.y), "r"(vh1.z), "r"(vh1.w));
                asm volatile("st.shared.v4.b32 [%0], {%1,%2,%3,%4};"
                             :: "r"(bufb + OFF_AL + s0), "r"(vl0.x), "r"(vl0.y), "r"(vl0.z), "r"(vl0.w));
                asm volatile("st.shared.v4.b32 [%0], {%1,%2,%3,%4};"
                             :: "r"(bufb + OFF_AL + s1), "r"(vl1.x), "r"(vl1.y), "r"(vl1.z), "r"(vl1.w));
            }
            {
#pragma unroll
                for (int j = 0; j < 4; j++) {
                    uint4 vh = *(const uint4*)(bcol_h + k0 + 8 * j);
                    const uint32_t so = swz128(b_base + 16 * j);
                    asm volatile("st.shared.v4.b32 [%0], {%1,%2,%3,%4};"
                                 :: "r"(bufb + OFF_BH + so), "r"(vh.x), "r"(vh.y), "r"(vh.z), "r"(vh.w));
                }
#pragma unroll
                for (int j = 0; j < 4; j++) {
                    uint4 vl = *(const uint4*)(bcol_l + k0 + 8 * j);
                    const uint32_t so = swz128(b_base + 16 * j);
                    asm volatile("st.shared.v4.b32 [%0], {%1,%2,%3,%4};"
                                 :: "r"(bufb + OFF_BL + so), "r"(vl.x), "r"(vl.y), "r"(vl.z), "r"(vl.w));
                }
            }

            fence_async_smem();
            __syncthreads();
            if (tid == 0) mbar_arrive_rank0(sb + SM_RDY + 8 * b);

            if (leader) {
                mbar_wait(sb + SM_RDY + 8 * b, rp[b]); rp[b] ^= 1;
                const uint64_t ah = desc_k_sw128(bufb + OFF_AH);
                const uint64_t al = desc_k_sw128(bufb + OFF_AL);
#pragma unroll
                for (int s = 0; s < 4; s++) {
                    const uint64_t as = (uint64_t)s * 2;
#pragma unroll
                    for (int nb = 0; nb < 4; nb++) {
                        const uint64_t bh  = desc_k_sw128(bufb + OFF_BH + nb * 8192) + as;
                        const uint64_t bls = desc_k_sw128(bufb + OFF_BL + nb * 8192) + as;
                        const uint32_t d = tm + nb * 128;
                        const uint32_t en0 = (c > 0 || s > 0) ? 1u : 0u;
                        tcg_mma2(d, ah + as, bh, en0);
                        tcg_mma2(d, ah + as, bls, 1u);
                        tcg_mma2(d, al + as, bh, 1u);
                    }
                }
                tcg_commit_mc2(sb + SM_DONE + 8 * b, 0x3);
                if (c == NC - 1) tcg_commit_mc2(sb + SM_TDONE, 0x3);
            }
        }

        // ---- tile epilogue ----
        mbar_wait(sb + SM_TDONE, tp); tp ^= 1;
        tcg_fence_after();

        const int wq = wid & 3, wg = wid >> 2;
        const int row = wq * 32 + lane;
        const int slot = pm0 + (int)rank * 128 + row;

        if (MODE == 0) {
            // gate tmem col = (wg>>1)*256 + (wg&1)*64; up = +128
            const uint32_t gc = (uint32_t)((wg >> 1) * 256 + (wg & 1) * 64);
            const int ocol = nblk * 256 + wg * 64;
            unsigned short* oh = g_hh + ((size_t)e * CAP + slot) * I_DIM + ocol;
            unsigned short* ol = g_hl + ((size_t)e * CAP + slot) * I_DIM + ocol;
#pragma unroll
            for (int half = 0; half < 2; half++) {
                uint32_t rg[32], ru[32];
                ldtm32(rg, tm + gc + half * 32);
                ldtm32(ru, tm + gc + 128 + half * 32);
                tcg_wait_ld();
#pragma unroll
                for (int j = 0; j < 16; j++) {
                    float g0 = __uint_as_float(rg[2*j]),   u0 = __uint_as_float(ru[2*j]);
                    float g1 = __uint_as_float(rg[2*j+1]), u1 = __uint_as_float(ru[2*j+1]);
                    float h0 = (g0 / (1.f + __expf(-g0))) * u0;
                    float h1 = (g1 / (1.f + __expf(-g1))) * u1;
                    unsigned short a0, a1, b0, b1;
                    split_bf16(h0, a0, b0);
                    split_bf16(h1, a1, b1);
                    ((uint32_t*)(oh + half * 32))[j] = (uint32_t)a0 | ((uint32_t)a1 << 16);
                    ((uint32_t*)(ol + half * 32))[j] = (uint32_t)b0 | ((uint32_t)b1 << 16);
                }
            }
        } else {
            const int ok = (slot < count);
            float wv = 0.f; int aid = 0;
            if (ok) { wv = g_wgt[e * CAP + slot]; aid = g_aid[e * CAP + slot]; }
            float* yp = g_y + (size_t)aid * H_DIM + nblk * 512 + wg * 128;
#pragma unroll
            for (int q = 0; q < 4; q++) {
                uint32_t r[32];
                ldtm32(r, tm + wg * 128 + q * 32);
                tcg_wait_ld();
                if (ok) {
#pragma unroll
                    for (int i = 0; i < 8; i++) {
                        float4 v;
                        v.x = __uint_as_float(r[4*i+0]) * wv;
                        v.y = __uint_as_float(r[4*i+1]) * wv;
                        v.z = __uint_as_float(r[4*i+2]) * wv;
                        v.w = __uint_as_float(r[4*i+3]) * wv;
                        *(float4*)&yp[q * 32 + 4 * i] = v;
                    }
                }
            }
        }
        tcg_fence_before();
        __syncthreads();
    }

    if (wid == 0) { tcg_relinq2(); tcg_dealloc2(tm, 512); }
    cluster_sync_();
#endif  // HAS_TCGEN05
}

// ---------------- combine (float4) ----------------
__global__ void combine_kernel(float* __restrict__ out) {
    const int idx = blockIdx.x * 256 + threadIdx.x;      // T*H/4 float4s
    const int t = idx / (H_DIM / 4);
    const int c4 = idx % (H_DIM / 4);
    const float4* yb = (const float4*)(g_y + ((size_t)t * K_TOP) * H_DIM) + c4;
    float4 s = make_float4(0.f, 0.f, 0.f, 0.f);
#pragma unroll
    for (int k = 0; k < K_TOP; k++) {
        float4 v = yb[(size_t)k * (H_DIM / 4)];
        s.x += v.x; s.y += v.y; s.z += v.z; s.w += v.w;
    }
    ((float4*)out)[idx] = s;
}

// ---------------- launch ----------------
extern "C" void kernel_launch(void* const* d_in, const int* in_sizes, int n_in,
                              void* d_out, int out_size) {
    const float* x  = (const float*)d_in[0];
    const float* gw = (const float*)d_in[1];
    const float* gb = (const float*)d_in[2];
    const float* w1 = (const float*)d_in[3];
    const float* w2 = (const float*)d_in[4];
    float* out = (float*)d_out;

    cudaFuncSetAttribute(gemm_tc2<0>, cudaFuncAttributeMaxDynamicSharedMemorySize, SMEM_TC);
    cudaFuncSetAttribute(gemm_tc2<1>, cudaFuncAttributeMaxDynamicSharedMemorySize, SMEM_TC);

    prep_kernel<<<256, 256>>>(gw);
    router_kernel<<<T_TOK, 256>>>(x, gb);
    plan_kernel<<<1, 64>>>();

    unsigned short *w1h, *w1l, *w2h, *w2l;
    cudaGetSymbolAddress((void**)&w1h, g_w1h);
    cudaGetSymbolAddress((void**)&w1l, g_w1l);
    cudaGetSymbolAddress((void**)&w2h, g_w2h);
    cudaGetSymbolAddress((void**)&w2l, g_w2l);

    conv_kernel<H_DIM, N1><<<dim3(H_DIM / 128, N1 / 64, E_NUM), 256>>>(w1, w1h, w1l);
    conv_kernel<I_DIM, H_DIM><<<dim3(I_DIM / 128, H_DIM / 64, E_NUM), 256>>>(w2, w2h, w2l);

    gemm_tc2<0><<<dim3(2, NCLUS, 1), 512, SMEM_TC>>>(x);
    gemm_tc2<1><<<dim3(2, NCLUS, 1), 512, SMEM_TC>>>(nullptr);

    combine_kernel<<<(T_TOK * H_DIM / 4) / 256, 256>>>(out);
}

// round 10
// speedup vs baseline: 1.0847x; 1.0847x over previous
#include <cuda_runtime.h>
#include <cuda_bf16.h>
#include <math.h>
#include <stdint.h>

#define T_TOK 2048
#define H_DIM 2048
#define I_DIM 768
#define E_NUM 32
#define K_TOP 8
#define CAP   1024
#define A_TOTAL (T_TOK * K_TOP)
#define N1 (2 * I_DIM)          // 1536

#define TPE1 12                 // gemm1 tiles/expert: 4 mpair x 3 nblk
#define TPE2 16                 // gemm2: 4 mpair x 4 nblk
#define NTIL1 (E_NUM * TPE1)    // 384
#define NTIL2 (E_NUM * TPE2)    // 512
#define NCLUS 74

#if defined(__CUDA_ARCH__)
#  if defined(__CUDA_ARCH_FEAT_SM103_ALL) || defined(__CUDA_ARCH_FEAT_SM100_ALL) || \
      (defined(__CUDA_ARCH_SPECIFIC__) && (__CUDA_ARCH_SPECIFIC__ == 1030 || __CUDA_ARCH_SPECIFIC__ == 1000))
#    define HAS_TCGEN05 1
#  else
#    define HAS_TCGEN05 0
#  endif
#else
#  define HAS_TCGEN05 0
#endif

// ---------------- device scratch ----------------
__device__ float g_gate_wT[E_NUM * H_DIM];
__device__ int   g_cnt[E_NUM];
__device__ int   g_tok[E_NUM * CAP];
__device__ int   g_aid[E_NUM * CAP];
__device__ float g_wgt[E_NUM * CAP];
__device__ int   g_pl1[NTIL1], g_pl2[NTIL2];
__device__ int   g_npl1, g_npl2;
__device__ unsigned short g_hh[(size_t)E_NUM * CAP * I_DIM];
__device__ unsigned short g_hl[(size_t)E_NUM * CAP * I_DIM];
__device__ float g_y[(size_t)A_TOTAL * H_DIM];
__device__ unsigned short g_w1h[(size_t)E_NUM * N1 * H_DIM];
__device__ unsigned short g_w1l[(size_t)E_NUM * N1 * H_DIM];
__device__ unsigned short g_w2h[(size_t)E_NUM * H_DIM * I_DIM];
__device__ unsigned short g_w2l[(size_t)E_NUM * H_DIM * I_DIM];

// ---------------- helpers ----------------
__device__ __forceinline__ void split_bf16(float x, unsigned short& h, unsigned short& l) {
    __nv_bfloat16 bh = __float2bfloat16_rn(x);
    h = *reinterpret_cast<unsigned short*>(&bh);
    float r = x - __bfloat162float(bh);
    __nv_bfloat16 bl = __float2bfloat16_rn(r);
    l = *reinterpret_cast<unsigned short*>(&bl);
}
__device__ __forceinline__ uint32_t smem_u32(const void* p) {
    return (uint32_t)__cvta_generic_to_shared(p);
}
__device__ __forceinline__ uint32_t swz128(uint32_t o) { return o ^ ((o >> 3) & 0x70); }

// ---------------- weight conversion (R8-proven 64-row tiles) ----------------
template<int KD, int ND>
__global__ __launch_bounds__(256) void conv_kernel(const float* __restrict__ W,
                                                   unsigned short* __restrict__ Wh,
                                                   unsigned short* __restrict__ Wl) {
    const int e = blockIdx.z;
    const int k0 = blockIdx.x * 64;
    const int n0 = blockIdx.y * 64;
    __shared__ float ts[64][65];
    const int tid = threadIdx.x;

    const int lr = tid >> 4, lc = (tid & 15) * 4;
    const float* src = W + (size_t)e * KD * ND + (size_t)k0 * ND + n0;
#pragma unroll
    for (int it = 0; it < 4; it++) {
        const int row = lr + it * 16;
        float4 v = *(const float4*)(src + (size_t)row * ND + lc);
        ts[row][lc + 0] = v.x; ts[row][lc + 1] = v.y;
        ts[row][lc + 2] = v.z; ts[row][lc + 3] = v.w;
    }
    __syncthreads();

    const int n = tid >> 2, ks = (tid & 3) * 16;
    uint32_t hh[8], ll[8];
#pragma unroll
    for (int q = 0; q < 8; q++) {
        unsigned short h0, h1, l0, l1;
        split_bf16(ts[ks + 2 * q][n],     h0, l0);
        split_bf16(ts[ks + 2 * q + 1][n], h1, l1);
        hh[q] = (uint32_t)h0 | ((uint32_t)h1 << 16);
        ll[q] = (uint32_t)l0 | ((uint32_t)l1 << 16);
    }
    const size_t doff = ((size_t)e * ND + n0 + n) * KD + k0 + ks;
    *(uint4*)(Wh + doff)     = make_uint4(hh[0], hh[1], hh[2], hh[3]);
    *(uint4*)(Wh + doff + 8) = make_uint4(hh[4], hh[5], hh[6], hh[7]);
    *(uint4*)(Wl + doff)     = make_uint4(ll[0], ll[1], ll[2], ll[3]);
    *(uint4*)(Wl + doff + 8) = make_uint4(ll[4], ll[5], ll[6], ll[7]);
}

// ---------------- prep ----------------
__global__ void prep_kernel(const float* __restrict__ gate_w) {
    int i = blockIdx.x * 256 + threadIdx.x;
    if (i < E_NUM * H_DIM) {
        int e = i >> 11;
        int h = i & (H_DIM - 1);
        g_gate_wT[i] = gate_w[h * E_NUM + e];
    }
    if (i < E_NUM) g_cnt[i] = 0;
}

// ---------------- router ----------------
__global__ __launch_bounds__(256) void router_kernel(const float* __restrict__ x,
                                                     const float* __restrict__ gate_b) {
    __shared__ float xs[H_DIM];
    __shared__ float lg[E_NUM];
    const int t = blockIdx.x;
    const int tid = threadIdx.x;

    const float4* xr = (const float4*)(x + (size_t)t * H_DIM);
    for (int i = tid; i < H_DIM / 4; i += 256) ((float4*)xs)[i] = xr[i];
    __syncthreads();

    const int w = tid >> 5, lane = tid & 31;
#pragma unroll
    for (int ee = 0; ee < 4; ee++) {
        const int e = (w << 2) + ee;
        const float* gw = g_gate_wT + (size_t)e * H_DIM;
        float s = 0.f;
        for (int h = lane; h < H_DIM; h += 32) s += xs[h] * gw[h];
#pragma unroll
        for (int off = 16; off; off >>= 1) s += __shfl_xor_sync(0xffffffffu, s, off);
        if (lane == 0) lg[e] = s + gate_b[e];
    }
    __syncthreads();

    if (tid == 0) {
        float mx = lg[0];
#pragma unroll
        for (int e = 1; e < E_NUM; e++) mx = fmaxf(mx, lg[e]);
        float p[E_NUM];
#pragma unroll
        for (int e = 0; e < E_NUM; e++) p[e] = __expf(lg[e] - mx);
        float vals[K_TOP]; int sel[K_TOP]; float vsum = 0.f;
#pragma unroll
        for (int k = 0; k < K_TOP; k++) {
            int bj = 0; float bv = p[0];
            for (int e = 1; e < E_NUM; e++) if (p[e] > bv) { bv = p[e]; bj = e; }
            sel[k] = bj; vals[k] = bv; vsum += bv; p[bj] = -1.f;
        }
        const float inv = 1.f / vsum;
#pragma unroll
        for (int k = 0; k < K_TOP; k++) {
            const int e = sel[k];
            int slot = atomicAdd(&g_cnt[e], 1);
            if (slot < CAP) {
                g_tok[e * CAP + slot] = t;
                g_aid[e * CAP + slot] = (t << 3) + k;
                g_wgt[e * CAP + slot] = vals[k] * inv;
            }
        }
    }
}

// ---------------- plan ----------------
__global__ void plan_kernel() {
    if (threadIdx.x == 0) {
        int n = 0;
        for (int tl = 0; tl < NTIL1; tl++) {
            int e = tl / TPE1, mpair = (tl % TPE1) & 3;
            if (mpair * 256 < g_cnt[e]) g_pl1[n++] = tl;
        }
        g_npl1 = n;
    } else if (threadIdx.x == 32) {
        int n = 0;
        for (int tl = 0; tl < NTIL2; tl++) {
            int e = tl / TPE2, mpair = (tl % TPE2) & 3;
            if (mpair * 256 < g_cnt[e]) g_pl2[n++] = tl;
        }
        g_npl2 = n;
    }
}

// ---------------- smem arena ----------------
#define SM_TMEMPTR 0
#define SM_RDY     16
#define SM_DONE    32
#define SM_TDONE   48
#define SM_TOKS    64
#define SM_BUF     1024
#define OFF_AH     0
#define OFF_AL     16384
#define OFF_BH     32768       // 2 nh blocks x (128 rows x 128B = 16KB)
#define OFF_BL     65536
#define BUF_SZ     98304
#define SMEM_TC    (SM_BUF + 2 * BUF_SZ)   // 197632

#if HAS_TCGEN05
__device__ __forceinline__ uint32_t elect_one() {
    uint32_t pred;
    asm volatile("{\n\t.reg .pred p;\n\telect.sync _|p, 0xFFFFFFFF;\n\tselp.b32 %0, 1, 0, p;\n\t}"
                 : "=r"(pred));
    return pred;
}
__device__ __forceinline__ uint32_t ctarank() {
    uint32_t r;
    asm("mov.u32 %0, %%cluster_ctarank;" : "=r"(r));
    return r;
}
__device__ __forceinline__ uint64_t desc_k_sw128(uint32_t addr) {
    return ((uint64_t)(addr >> 4) & 0x3FFF) | (1ull << 16) | (64ull << 32)
         | (1ull << 46) | (2ull << 61);
}
// idesc kind::f16 cg2: dtype=F32, atype=BF16, btype=BF16, N=256, M=256
#define MMA_IDESC2 ((1u << 4) | (1u << 7) | (1u << 10) | ((256u / 8) << 17) | ((256u / 16) << 24))

__device__ __forceinline__ void tcg_mma2(uint32_t d, uint64_t a, uint64_t b, uint32_t en) {
    asm volatile(
        "{\n\t.reg .pred p;\n\tsetp.ne.u32 p, %4, 0;\n\t"
        "tcgen05.mma.cta_group::2.kind::f16 [%0], %1, %2, %3, "
        "{%5, %5, %5, %5, %5, %5, %5, %5}, p;\n\t}"
        :: "r"(d), "l"(a), "l"(b), "r"(MMA_IDESC2), "r"(en), "r"(0u) : "memory");
}
__device__ __forceinline__ void tcg_commit_mc2(uint32_t mbar, uint16_t mask) {
    asm volatile(
        "tcgen05.commit.cta_group::2.mbarrier::arrive::one.shared::cluster.multicast::cluster.b64 [%0], %1;"
        :: "r"(mbar), "h"(mask) : "memory");
}
__device__ __forceinline__ void tcg_alloc2(uint32_t smem_res, uint32_t ncols) {
    asm volatile("tcgen05.alloc.cta_group::2.sync.aligned.shared::cta.b32 [%0], %1;"
                 :: "r"(smem_res), "r"(ncols) : "memory");
}
__device__ __forceinline__ void tcg_dealloc2(uint32_t tmem, uint32_t ncols) {
    asm volatile("tcgen05.dealloc.cta_group::2.sync.aligned.b32 %0, %1;" :: "r"(tmem), "r"(ncols));
}
__device__ __forceinline__ void tcg_relinq2() {
    asm volatile("tcgen05.relinquish_alloc_permit.cta_group::2.sync.aligned;");
}
__device__ __forceinline__ void mbar_init(uint32_t mbar, uint32_t cnt) {
    asm volatile("mbarrier.init.shared.b64 [%0], %1;" :: "r"(mbar), "r"(cnt) : "memory");
}
__device__ __forceinline__ void mbar_arrive_rank0(uint32_t addr) {
    asm volatile(
        "{\n\t.reg .b32 r;\n\t"
        "mapa.shared::cluster.u32 r, %0, 0;\n\t"
        "mbarrier.arrive.shared::cluster.b64 _, [r];\n\t}"
        :: "r"(addr) : "memory");
}
__device__ __forceinline__ void mbar_wait(uint32_t mbar, uint32_t parity) {
    uint32_t done;
    asm volatile(
        "{\n\t.reg .pred p;\n\t"
        "mbarrier.try_wait.parity.acquire.cta.shared::cta.b64 p, [%1], %2;\n\t"
        "selp.b32 %0, 1, 0, p;\n\t}"
        : "=r"(done) : "r"(mbar), "r"(parity) : "memory");
    if (!done) {
        asm volatile(
            "{\n\t.reg .pred P1;\n\t"
            "WAIT_LOOP_%=:\n\t"
            "mbarrier.try_wait.parity.acquire.cta.shared::cta.b64 P1, [%0], %1, 0x989680;\n\t"
            "@P1 bra.uni WAIT_DONE_%=;\n\t"
            "bra.uni WAIT_LOOP_%=;\n\t"
            "WAIT_DONE_%=:\n\t}"
            :: "r"(mbar), "r"(parity) : "memory");
    }
}
__device__ __forceinline__ void fence_async_smem() {
    asm volatile("fence.proxy.async.shared::cta;" ::: "memory");
}
__device__ __forceinline__ void tcg_fence_after() {
    asm volatile("tcgen05.fence::after_thread_sync;" ::: "memory");
}
__device__ __forceinline__ void tcg_fence_before() {
    asm volatile("tcgen05.fence::before_thread_sync;" ::: "memory");
}
__device__ __forceinline__ void tcg_wait_ld() {
    asm volatile("tcgen05.wait::ld.sync.aligned;" ::: "memory");
}
__device__ __forceinline__ void cluster_sync_() {
    asm volatile("barrier.cluster.arrive.aligned;" ::: "memory");
    asm volatile("barrier.cluster.wait.aligned;" ::: "memory");
}
__device__ __forceinline__ void ldtm32(uint32_t* r, uint32_t addr) {
    asm volatile(
        "tcgen05.ld.sync.aligned.32x32b.x32.b32 "
        "{%0, %1, %2, %3, %4, %5, %6, %7, "
        " %8, %9, %10, %11, %12, %13, %14, %15, "
        " %16, %17, %18, %19, %20, %21, %22, %23, "
        " %24, %25, %26, %27, %28, %29, %30, %31}, [%32];"
        : "=r"(r[0]),  "=r"(r[1]),  "=r"(r[2]),  "=r"(r[3]),
          "=r"(r[4]),  "=r"(r[5]),  "=r"(r[6]),  "=r"(r[7]),
          "=r"(r[8]),  "=r"(r[9]),  "=r"(r[10]), "=r"(r[11]),
          "=r"(r[12]), "=r"(r[13]), "=r"(r[14]), "=r"(r[15]),
          "=r"(r[16]), "=r"(r[17]), "=r"(r[18]), "=r"(r[19]),
          "=r"(r[20]), "=r"(r[21]), "=r"(r[22]), "=r"(r[23]),
          "=r"(r[24]), "=r"(r[25]), "=r"(r[26]), "=r"(r[27]),
          "=r"(r[28]), "=r"(r[29]), "=r"(r[30]), "=r"(r[31])
        : "r"(addr));
}
#endif  // HAS_TCGEN05

// Persistent 2-CTA tcgen05 grouped GEMM, bf16x3, BM=256/BN=512/Kc=64, N=256/dispatch.
// grid (2, 74, 1), cluster (2,1,1). Tiles from compacted plan.
// D col c (0..511): c = nh*256 + rank*128 + lr. gemm1 global B col layout per tile:
//   [gate_p0(0-127), up_p0(128-255), gate_p1(256-383), up_p1(384-511)]
//   -> p = nh, is_up = rank, i = lr  (epilogue mapping identical to validated R9)
template<int MODE>
__global__ __launch_bounds__(512) __cluster_dims__(2, 1, 1)
void gemm_tc2(const float* __restrict__ X) {
#if HAS_TCGEN05
    constexpr int KDIM = MODE ? I_DIM : H_DIM;
    constexpr int NC   = KDIM / 64;
    constexpr int TPE  = MODE ? TPE2 : TPE1;

    const uint32_t rank = ctarank();
    const int tid = threadIdx.x;
    const int wid = tid >> 5, lane = tid & 31;

    extern __shared__ __align__(1024) char smem[];
    const uint32_t sb = smem_u32(smem);

    if (wid == 0) tcg_alloc2(sb + SM_TMEMPTR, 512);
    if (tid == 0) {
        mbar_init(sb + SM_RDY, 2);      mbar_init(sb + SM_RDY + 8, 2);
        mbar_init(sb + SM_DONE, 1);     mbar_init(sb + SM_DONE + 8, 1);
        mbar_init(sb + SM_TDONE, 1);
    }
    __syncthreads();
    uint32_t tm;
    asm volatile("ld.shared.b32 %0, [%1];" : "=r"(tm) : "r"(sb + SM_TMEMPTR));
    cluster_sync_();

    uint32_t leader = 0;
    if (rank == 0 && wid == 0) leader = elect_one();

    const int ntiles = MODE ? g_npl2 : g_npl1;
    const int* plan  = MODE ? g_pl2 : g_pl1;

    const int arow = tid >> 2, akq = (tid & 3) * 16;
    const uint32_t a_base = (uint32_t)arow * 128 + (uint32_t)akq * 2;
    const int bl = tid >> 1, bkh = (tid & 1) * 32;
    const int nh = bl >> 7, lr = bl & 127;
    const uint32_t b_base = (uint32_t)bl * 128 + (uint32_t)bkh * 2;

    int cc = 0, dp[2] = {0, 0}, rp[2] = {0, 0}, tp = 0;

    for (int ti = blockIdx.y; ti < ntiles; ti += NCLUS) {
        const int tl = plan[ti];
        const int e = tl / TPE, rr = tl % TPE;
        const int mpair = rr & 3, nblk = rr >> 2;
        const int count = g_cnt[e];
        const int pm0 = mpair * 256;

        // ---- per-tile pointers ----
        const float* arow_f = nullptr;
        const unsigned short *arow_h = nullptr, *arow_l = nullptr;
        if (MODE == 0) {
            if (tid < 128) {
                int s = pm0 + (int)rank * 128 + tid; if (s >= count) s = count - 1;
                ((int*)(smem + SM_TOKS))[tid] = g_tok[e * CAP + s];
            }
            __syncthreads();
            arow_f = X + (size_t)((int*)(smem + SM_TOKS))[arow] * H_DIM + akq;
        } else {
            int s = pm0 + (int)rank * 128 + arow; if (s >= count) s = count - 1;
            size_t off = ((size_t)e * CAP + s) * I_DIM + akq;
            arow_h = g_hh + off; arow_l = g_hl + off;
        }
        int gcol;
        if (MODE == 0) {
            gcol = ((int)rank ? I_DIM : 0) + nblk * 256 + nh * 128 + lr;
        } else {
            gcol = nblk * 512 + nh * 256 + (int)rank * 128 + lr;
        }
        const unsigned short *bcol_h, *bcol_l;
        if (MODE == 0) {
            size_t off = ((size_t)e * N1 + gcol) * H_DIM + bkh;
            bcol_h = g_w1h + off; bcol_l = g_w1l + off;
        } else {
            size_t off = ((size_t)e * H_DIM + gcol) * I_DIM + bkh;
            bcol_h = g_w2h + off; bcol_l = g_w2l + off;
        }

        // ---- chunk pipeline ----
        for (int c = 0; c < NC; c++, cc++) {
            const int b = cc & 1;
            if (cc >= 2) { mbar_wait(sb + SM_DONE + 8 * b, dp[b]); dp[b] ^= 1; }
            const uint32_t bufb = sb + SM_BUF + b * BUF_SZ;
            const int k0 = c * 64;

            if (MODE == 0) {
                float4 v0 = *(const float4*)(arow_f + k0);
                float4 v1 = *(const float4*)(arow_f + k0 + 4);
                float4 v2 = *(const float4*)(arow_f + k0 + 8);
                float4 v3 = *(const float4*)(arow_f + k0 + 12);
                float vv[16] = {v0.x,v0.y,v0.z,v0.w, v1.x,v1.y,v1.z,v1.w,
                                v2.x,v2.y,v2.z,v2.w, v3.x,v3.y,v3.z,v3.w};
                uint32_t hh[8], ll[8];
#pragma unroll
                for (int q = 0; q < 8; q++) {
                    unsigned short h0, h1, l0, l1;
                    split_bf16(vv[2*q],   h0, l0);
                    split_bf16(vv[2*q+1], h1, l1);
                    hh[q] = (uint32_t)h0 | ((uint32_t)h1 << 16);
                    ll[q] = (uint32_t)l0 | ((uint32_t)l1 << 16);
                }
                const uint32_t s0 = swz128(a_base), s1 = swz128(a_base + 16);
                asm volatile("st.shared.v4.b32 [%0], {%1,%2,%3,%4};"
                             :: "r"(bufb + OFF_AH + s0), "r"(hh[0]), "r"(hh[1]), "r"(hh[2]), "r"(hh[3]));
                asm volatile("st.shared.v4.b32 [%0], {%1,%2,%3,%4};"
                             :: "r"(bufb + OFF_AH + s1), "r"(hh[4]), "r"(hh[5]), "r"(hh[6]), "r"(hh[7]));
                asm volatile("st.shared.v4.b32 [%0], {%1,%2,%3,%4};"
                             :: "r"(bufb + OFF_AL + s0), "r"(ll[0]), "r"(ll[1]), "r"(ll[2]), "r"(ll[3]));
                asm volatile("st.shared.v4.b32 [%0], {%1,%2,%3,%4};"
                             :: "r"(bufb + OFF_AL + s1), "r"(ll[4]), "r"(ll[5]), "r"(ll[6]), "r"(ll[7]));
            } else {
                uint4 vh0 = *(const uint4*)(arow_h + k0);
                uint4 vh1 = *(const uint4*)(arow_h + k0 + 8);
                uint4 vl0 = *(const uint4*)(arow_l + k0);
                uint4 vl1 = *(const uint4*)(arow_l + k0 + 8);
                const uint32_t s0 = swz128(a_base), s1 = swz128(a_base + 16);
                asm volatile("st.shared.v4.b32 [%0], {%1,%2,%3,%4};"
                             :: "r"(bufb + OFF_AH + s0), "r"(vh0.x), "r"(vh0.y), "r"(vh0.z), "r"(vh0.w));
                asm volatile("st.shared.v4.b32 [%0], {%1,%2,%3,%4};"
                             :: "r"(bufb + OFF_AH + s1), "r"(vh1.x), "r"(vh1.y), "r"(vh1.z), "r"(vh1.w));
                asm volatile("st.shared.v4.b32 [%0], {%1,%2,%3,%4};"
                             :: "r"(bufb + OFF_AL + s0), "r"(vl0.x), "r"(vl0.y), "r"(vl0.z), "r"(vl0.w));
                asm volatile("st.shared.v4.b32 [%0], {%1,%2,%3,%4};"
                             :: "r"(bufb + OFF_AL + s1), "r"(vl1.x), "r"(vl1.y), "r"(vl1.z), "r"(vl1.w));
            }
            {
#pragma unroll
                for (int j = 0; j < 4; j++) {
                    uint4 vh = *(const uint4*)(bcol_h + k0 + 8 * j);
                    const uint32_t so = swz128(b_base + 16 * j);
                    asm volatile("st.shared.v4.b32 [%0], {%1,%2,%3,%4};"
                                 :: "r"(bufb + OFF_BH + so), "r"(vh.x), "r"(vh.y), "r"(vh.z), "r"(vh.w));
                }
#pragma unroll
                for (int j = 0; j < 4; j++) {
                    uint4 vl = *(const uint4*)(bcol_l + k0 + 8 * j);
                    const uint32_t so = swz128(b_base + 16 * j);
                    asm volatile("st.shared.v4.b32 [%0], {%1,%2,%3,%4};"
                                 :: "r"(bufb + OFF_BL + so), "r"(vl.x), "r"(vl.y), "r"(vl.z), "r"(vl.w));
                }
            }

            fence_async_smem();
            __syncthreads();
            if (tid == 0) mbar_arrive_rank0(sb + SM_RDY + 8 * b);

            if (leader) {
                mbar_wait(sb + SM_RDY + 8 * b, rp[b]); rp[b] ^= 1;
                const uint64_t ah = desc_k_sw128(bufb + OFF_AH);
                const uint64_t al = desc_k_sw128(bufb + OFF_AL);
#pragma unroll
                for (int s = 0; s < 4; s++) {
                    const uint64_t as = (uint64_t)s * 2;
#pragma unroll
                    for (int nhd = 0; nhd < 2; nhd++) {
                        const uint64_t bh  = desc_k_sw128(bufb + OFF_BH + nhd * 16384) + as;
                        const uint64_t bls = desc_k_sw128(bufb + OFF_BL + nhd * 16384) + as;
                        const uint32_t d = tm + nhd * 256;
                        const uint32_t en0 = (c > 0 || s > 0) ? 1u : 0u;
                        tcg_mma2(d, ah + as, bh, en0);
                        tcg_mma2(d, ah + as, bls, 1u);
                        tcg_mma2(d, al + as, bh, 1u);
                    }
                }
                tcg_commit_mc2(sb + SM_DONE + 8 * b, 0x3);
                if (c == NC - 1) tcg_commit_mc2(sb + SM_TDONE, 0x3);
            }
        }

        // ---- tile epilogue ----
        mbar_wait(sb + SM_TDONE, tp); tp ^= 1;
        tcg_fence_after();

        const int wq = wid & 3, wg = wid >> 2;
        const int row = wq * 32 + lane;
        const int slot = pm0 + (int)rank * 128 + row;

        if (MODE == 0) {
            // gate tmem col = (wg>>1)*256 + (wg&1)*64; up = +128 (same as R9)
            const uint32_t gc = (uint32_t)((wg >> 1) * 256 + (wg & 1) * 64);
            const int ocol = nblk * 256 + wg * 64;
            unsigned short* oh = g_hh + ((size_t)e * CAP + slot) * I_DIM + ocol;
            unsigned short* ol = g_hl + ((size_t)e * CAP + slot) * I_DIM + ocol;
#pragma unroll
            for (int half = 0; half < 2; half++) {
                uint32_t rg[32], ru[32];
                ldtm32(rg, tm + gc + half * 32);
                ldtm32(ru, tm + gc + 128 + half * 32);
                tcg_wait_ld();
#pragma unroll
                for (int j = 0; j < 16; j++) {
                    float g0 = __uint_as_float(rg[2*j]),   u0 = __uint_as_float(ru[2*j]);
                    float g1 = __uint_as_float(rg[2*j+1]), u1 = __uint_as_float(ru[2*j+1]);
                    float h0 = (g0 / (1.f + __expf(-g0))) * u0;
                    float h1 = (g1 / (1.f + __expf(-g1))) * u1;
                    unsigned short a0, a1, b0, b1;
                    split_bf16(h0, a0, b0);
                    split_bf16(h1, a1, b1);
                    ((uint32_t*)(oh + half * 32))[j] = (uint32_t)a0 | ((uint32_t)a1 << 16);
                    ((uint32_t*)(ol + half * 32))[j] = (uint32_t)b0 | ((uint32_t)b1 << 16);
                }
            }
        } else {
            const int ok = (slot < count);
            float wv = 0.f; int aid = 0;
            if (ok) { wv = g_wgt[e * CAP + slot]; aid = g_aid[e * CAP + slot]; }
            float* yp = g_y + (size_t)aid * H_DIM + nblk * 512 + wg * 128;
#pragma unroll
            for (int q = 0; q < 4; q++) {
                uint32_t r[32];
                ldtm32(r, tm + wg * 128 + q * 32);
                tcg_wait_ld();
                if (ok) {
#pragma unroll
                    for (int i = 0; i < 8; i++) {
                        float4 v;
                        v.x = __uint_as_float(r[4*i+0]) * wv;
                        v.y = __uint_as_float(r[4*i+1]) * wv;
                        v.z = __uint_as_float(r[4*i+2]) * wv;
                        v.w = __uint_as_float(r[4*i+3]) * wv;
                        *(float4*)&yp[q * 32 + 4 * i] = v;
                    }
                }
            }
        }
        tcg_fence_before();
        __syncthreads();
    }

    if (wid == 0) { tcg_relinq2(); tcg_dealloc2(tm, 512); }
    cluster_sync_();
#endif  // HAS_TCGEN05
}

// ---------------- combine (float4) ----------------
__global__ void combine_kernel(float* __restrict__ out) {
    const int idx = blockIdx.x * 256 + threadIdx.x;
    const int t = idx / (H_DIM / 4);
    const int c4 = idx % (H_DIM / 4);
    const float4* yb = (const float4*)(g_y + ((size_t)t * K_TOP) * H_DIM) + c4;
    float4 s = make_float4(0.f, 0.f, 0.f, 0.f);
#pragma unroll
    for (int k = 0; k < K_TOP; k++) {
        float4 v = yb[(size_t)k * (H_DIM / 4)];
        s.x += v.x; s.y += v.y; s.z += v.z; s.w += v.w;
    }
    ((float4*)out)[idx] = s;
}

// ---------------- launch ----------------
extern "C" void kernel_launch(void* const* d_in, const int* in_sizes, int n_in,
                              void* d_out, int out_size) {
    const float* x  = (const float*)d_in[0];
    const float* gw = (const float*)d_in[1];
    const float* gb = (const float*)d_in[2];
    const float* w1 = (const float*)d_in[3];
    const float* w2 = (const float*)d_in[4];
    float* out = (float*)d_out;

    cudaFuncSetAttribute(gemm_tc2<0>, cudaFuncAttributeMaxDynamicSharedMemorySize, SMEM_TC);
    cudaFuncSetAttribute(gemm_tc2<1>, cudaFuncAttributeMaxDynamicSharedMemorySize, SMEM_TC);

    prep_kernel<<<256, 256>>>(gw);
    router_kernel<<<T_TOK, 256>>>(x, gb);
    plan_kernel<<<1, 64>>>();

    unsigned short *w1h, *w1l, *w2h, *w2l;
    cudaGetSymbolAddress((void**)&w1h, g_w1h);
    cudaGetSymbolAddress((void**)&w1l, g_w1l);
    cudaGetSymbolAddress((void**)&w2h, g_w2h);
    cudaGetSymbolAddress((void**)&w2l, g_w2l);

    conv_kernel<H_DIM, N1><<<dim3(H_DIM / 64, N1 / 64, E_NUM), 256>>>(w1, w1h, w1l);
    conv_kernel<I_DIM, H_DIM><<<dim3(I_DIM / 64, H_DIM / 64, E_NUM), 256>>>(w2, w2h, w2l);

    gemm_tc2<0><<<dim3(2, NCLUS, 1), 512, SMEM_TC>>>(x);
    gemm_tc2<1><<<dim3(2, NCLUS, 1), 512, SMEM_TC>>>(nullptr);

    combine_kernel<<<(T_TOK * H_DIM / 4) / 256, 256>>>(out);
}